// round 1
// baseline (speedup 1.0000x reference)
#include <cuda_runtime.h>
#include <cstdint>

// SegmentedPolynomialIndexedLinear: y[z] = coeff * x[z] @ W[idx[z]]
//   W: [C, U*V] fp32, x: [Z, U] fp32, idx: [Z] int32 (sorted), coeff: [1] fp32
//   C=8, U=512, V=512, Z=32768. Output y: [Z, V] fp32.
//
// Strategy (round 1 baseline): classic double-buffered fp32 SGEMM,
// 128x128 block tile, BK=16, 256 threads, 8x8 per-thread micro-tile
// (split 4+4 in both dims for conflict-free float4 smem reads).
// idx is sorted, so a 128-row tile spans a contiguous group range [g0,g1];
// g1>g0 happens in at most 7 of 256 M-tiles. Each block loops over the
// groups in its range, masking A rows (idx != g -> 0) at smem load,
// accumulating into persistent registers.

namespace {
constexpr int Cc = 8;
constexpr int Uc = 512;
constexpr int Vc = 512;
constexpr int Zc = 32768;

constexpr int BM = 128;
constexpr int BN = 128;
constexpr int BK = 16;
constexpr int APAD = 132;  // BM+4: row stride %32==4 (cheap store conflicts), 16B-aligned rows
constexpr int NTHREADS = 256;
}

__global__ __launch_bounds__(NTHREADS, 2)
void grouped_sgemm_kernel(const float* __restrict__ X,
                          const float* __restrict__ W,
                          const int*   __restrict__ IDX,
                          const float* __restrict__ COEF,
                          float*       __restrict__ Y)
{
    __shared__ float As[2][BK][APAD];
    __shared__ float Bs[2][BK][BN];
    __shared__ int   sidx[BM];

    const int tid = threadIdx.x;
    const int m0  = blockIdx.y * BM;
    const int n0  = blockIdx.x * BN;

    if (tid < BM) sidx[tid] = IDX[m0 + tid];
    __syncthreads();
    const int g0 = sidx[0];
    const int g1 = sidx[BM - 1];

    // micro-tile mapping: 16x16 thread grid; rows {ty*4+i, 64+ty*4+i},
    // cols {tx*4+j, 64+tx*4+j}
    const int tx = tid & 15;
    const int ty = tid >> 4;

    // A tile loaders: 512 float4 per 128x16 tile; thread handles f=tid, f=tid+256
    const int a_row = tid >> 2;          // 0..63
    const int a_col = (tid & 3) << 2;    // 0,4,8,12
    // B tile loaders: 512 float4 per 16x128 tile; f=tid -> row tid>>5, f=tid+256 -> +8
    const int b_row = tid >> 5;          // 0..7
    const int b_col = (tid & 31) << 2;   // 0..124

    const float* Xa0 = X + (size_t)(m0 + a_row)      * Uc + a_col;
    const float* Xa1 = X + (size_t)(m0 + a_row + 64) * Uc + a_col;

    float acc[8][8];
#pragma unroll
    for (int i = 0; i < 8; ++i)
#pragma unroll
        for (int j = 0; j < 8; ++j) acc[i][j] = 0.f;

    for (int g = g0; g <= g1; ++g) {
        const float* Wg = W + (size_t)g * Uc * Vc;
        const bool ok0 = (sidx[a_row]      == g);
        const bool ok1 = (sidx[a_row + 64] == g);

        // ---- prologue: k-tile 0 into buffer 0 ----
        {
            float4 v0 = *(const float4*)(Xa0);
            float4 v1 = *(const float4*)(Xa1);
            if (!ok0) v0 = make_float4(0.f, 0.f, 0.f, 0.f);
            if (!ok1) v1 = make_float4(0.f, 0.f, 0.f, 0.f);
            As[0][a_col + 0][a_row] = v0.x;
            As[0][a_col + 1][a_row] = v0.y;
            As[0][a_col + 2][a_row] = v0.z;
            As[0][a_col + 3][a_row] = v0.w;
            As[0][a_col + 0][a_row + 64] = v1.x;
            As[0][a_col + 1][a_row + 64] = v1.y;
            As[0][a_col + 2][a_row + 64] = v1.z;
            As[0][a_col + 3][a_row + 64] = v1.w;

            float4 w0 = *(const float4*)(Wg + (size_t)(b_row)     * Vc + n0 + b_col);
            float4 w1 = *(const float4*)(Wg + (size_t)(b_row + 8) * Vc + n0 + b_col);
            *(float4*)&Bs[0][b_row][b_col]     = w0;
            *(float4*)&Bs[0][b_row + 8][b_col] = w1;
        }
        __syncthreads();

        int buf = 0;
        constexpr int KT = Uc / BK;  // 32
#pragma unroll 1
        for (int kt = 0; kt < KT; ++kt) {
            // ---- prefetch next k-tile into other buffer ----
            if (kt + 1 < KT) {
                const int k0 = (kt + 1) * BK;
                float4 v0 = *(const float4*)(Xa0 + k0);
                float4 v1 = *(const float4*)(Xa1 + k0);
                if (!ok0) v0 = make_float4(0.f, 0.f, 0.f, 0.f);
                if (!ok1) v1 = make_float4(0.f, 0.f, 0.f, 0.f);
                const int nb = buf ^ 1;
                As[nb][a_col + 0][a_row] = v0.x;
                As[nb][a_col + 1][a_row] = v0.y;
                As[nb][a_col + 2][a_row] = v0.z;
                As[nb][a_col + 3][a_row] = v0.w;
                As[nb][a_col + 0][a_row + 64] = v1.x;
                As[nb][a_col + 1][a_row + 64] = v1.y;
                As[nb][a_col + 2][a_row + 64] = v1.z;
                As[nb][a_col + 3][a_row + 64] = v1.w;

                float4 w0 = *(const float4*)(Wg + (size_t)(k0 + b_row)     * Vc + n0 + b_col);
                float4 w1 = *(const float4*)(Wg + (size_t)(k0 + b_row + 8) * Vc + n0 + b_col);
                *(float4*)&Bs[nb][b_row][b_col]     = w0;
                *(float4*)&Bs[nb][b_row + 8][b_col] = w1;
            }

            // ---- compute current buffer ----
#pragma unroll
            for (int k = 0; k < BK; ++k) {
                float4 a0 = *(const float4*)&As[buf][k][(ty << 2)];
                float4 a1 = *(const float4*)&As[buf][k][64 + (ty << 2)];
                float4 bb0 = *(const float4*)&Bs[buf][k][(tx << 2)];
                float4 bb1 = *(const float4*)&Bs[buf][k][64 + (tx << 2)];
                float av[8] = {a0.x, a0.y, a0.z, a0.w, a1.x, a1.y, a1.z, a1.w};
                float bv[8] = {bb0.x, bb0.y, bb0.z, bb0.w, bb1.x, bb1.y, bb1.z, bb1.w};
#pragma unroll
                for (int i = 0; i < 8; ++i)
#pragma unroll
                    for (int j = 0; j < 8; ++j)
                        acc[i][j] = fmaf(av[i], bv[j], acc[i][j]);
            }
            __syncthreads();
            buf ^= 1;
        }
        // final __syncthreads above guarantees buffers reusable next pass
    }

    const float scale = COEF[0];

#pragma unroll
    for (int ih = 0; ih < 2; ++ih) {
#pragma unroll
        for (int i = 0; i < 4; ++i) {
            const int r  = m0 + ih * 64 + (ty << 2) + i;
            const int ai = ih * 4 + i;
            float4 o0, o1;
            o0.x = acc[ai][0] * scale;
            o0.y = acc[ai][1] * scale;
            o0.z = acc[ai][2] * scale;
            o0.w = acc[ai][3] * scale;
            o1.x = acc[ai][4] * scale;
            o1.y = acc[ai][5] * scale;
            o1.z = acc[ai][6] * scale;
            o1.w = acc[ai][7] * scale;
            *(float4*)(Y + (size_t)r * Vc + n0 + (tx << 2))      = o0;
            *(float4*)(Y + (size_t)r * Vc + n0 + 64 + (tx << 2)) = o1;
        }
    }
}

extern "C" void kernel_launch(void* const* d_in, const int* in_sizes, int n_in,
                              void* d_out, int out_size)
{
    // Identify inputs by element count (all four are distinct):
    //   w: C*U*V = 2097152, x: Z*U = 16777216, idx: Z = 32768, coeff: 1
    const float* w    = nullptr;
    const float* x    = nullptr;
    const int*   idx  = nullptr;
    const float* coef = nullptr;
    for (int i = 0; i < n_in; ++i) {
        const long long sz = in_sizes[i];
        if      (sz == (long long)Cc * Uc * Vc) w    = (const float*)d_in[i];
        else if (sz == (long long)Zc * Uc)      x    = (const float*)d_in[i];
        else if (sz == (long long)Zc)           idx  = (const int*)d_in[i];
        else if (sz == 1)                       coef = (const float*)d_in[i];
    }
    // Fallback to metadata order: w, x, idx, coefficients
    if (!w    && n_in > 0) w    = (const float*)d_in[0];
    if (!x    && n_in > 1) x    = (const float*)d_in[1];
    if (!idx  && n_in > 2) idx  = (const int*)d_in[2];
    if (!coef && n_in > 3) coef = (const float*)d_in[3];

    float* y = (float*)d_out;

    dim3 grid(Vc / BN, Zc / BM);   // (4, 256)
    dim3 block(NTHREADS);
    grouped_sgemm_kernel<<<grid, block>>>(x, w, idx, coef, y);
}

// round 4
// speedup vs baseline: 2.9558x; 2.9558x over previous
#include <cuda_runtime.h>
#include <cstdint>

// SegmentedPolynomialIndexedLinear: y[z] = coeff * x[z] @ W[idx[z]]
//   W:[C,U*V] fp32, x:[Z,U] fp32, idx:[Z] int32 sorted, coeff:[1]. C=8,U=V=512,Z=32768.
//
// Harness compiles PTX at target compute_100 (no 'a'), so tcgen05 is unavailable.
// Use preserved warp-level mma.sync m16n8k8 tf32 (sm_80+) + cp.async:
//   BM=128 BN=128 BK=16, 8 warps (2x4), warp tile 64x32, 2-stage cp.async
//   pipeline, zfill-masked A rows for the sorted-group raggedness,
//   cvt.rna.tf32 on fragments (round-nearest, avoids RZ truncation bias).

namespace {
constexpr int Cc = 8, Uc = 512, Vc = 512, Zc = 32768;
constexpr int BM = 128, BN = 128, BK = 16;
constexpr int BKP = 20;    // A row pad: (20*lr+lq)%32 permutes -> conflict-free frags
constexpr int BNP = 136;   // B row pad: (8*lq+lr)%32 permutes -> conflict-free frags
constexpr int NT  = 256;
constexpr int KT  = Uc / BK;   // 32 k-tiles
}

#define DEVFN __device__ __forceinline__

DEVFN uint32_t smem_u32(const void* p) {
    uint32_t a;
    asm("{ .reg .u64 t; cvta.to.shared.u64 t, %1; cvt.u32.u64 %0, t; }"
        : "=r"(a) : "l"(p));
    return a;
}
DEVFN uint32_t f2tf(float f) {
    uint32_t u;
    asm("cvt.rna.tf32.f32 %0, %1;" : "=r"(u) : "f"(f));
    return u;
}
DEVFN void cp16(uint32_t dst, const void* src, int srcbytes) {
    asm volatile("cp.async.cg.shared.global [%0], [%1], 16, %2;"
                 :: "r"(dst), "l"(src), "r"(srcbytes) : "memory");
}
DEVFN void cp_commit() { asm volatile("cp.async.commit_group;" ::: "memory"); }
template <int N> DEVFN void cp_wait() {
    asm volatile("cp.async.wait_group %0;" :: "n"(N) : "memory");
}
DEVFN void mma_tf32(float* d, const uint32_t* a, const uint32_t* b) {
    asm volatile(
        "mma.sync.aligned.m16n8k8.row.col.f32.tf32.tf32.f32 "
        "{%0,%1,%2,%3}, {%4,%5,%6,%7}, {%8,%9}, {%0,%1,%2,%3};"
        : "+f"(d[0]), "+f"(d[1]), "+f"(d[2]), "+f"(d[3])
        : "r"(a[0]), "r"(a[1]), "r"(a[2]), "r"(a[3]), "r"(b[0]), "r"(b[1]));
}

__global__ void __launch_bounds__(NT, 2)
grouped_mma_kernel(const float* __restrict__ X,
                   const float* __restrict__ W,
                   const int*   __restrict__ IDX,
                   const float* __restrict__ COEF,
                   float*       __restrict__ Y)
{
    __shared__ float As[2][BM][BKP];   // 20480 B
    __shared__ float Bs[2][BK][BNP];   // 17408 B
    __shared__ int   sidx[BM];

    const int tid = threadIdx.x;
    const int m0  = blockIdx.y * BM;
    const int n0  = blockIdx.x * BN;

    if (tid < BM) sidx[tid] = IDX[m0 + tid];
    __syncthreads();
    const int g0 = sidx[0];
    const int g1 = sidx[BM - 1];

    const int wid  = tid >> 5, lane = tid & 31;
    const int wm   = wid >> 2, wn   = wid & 3;     // warp grid 2 x 4
    const int lr   = lane >> 2, lq  = lane & 3;

    // cp.async loader mapping
    const int a_row = tid >> 2;           // 0..63 (+64)
    const int a_col = (tid & 3) << 2;     // 0,4,8,12 (k offset)
    const int b_row = tid >> 5;           // 0..7 (+8)
    const int b_col = (tid & 31) << 2;    // 0..124

    const uint32_t aD0 = smem_u32(&As[0][a_row][a_col]);
    const uint32_t aD1 = smem_u32(&As[0][a_row + 64][a_col]);
    const uint32_t bD0 = smem_u32(&Bs[0][b_row][b_col]);
    const uint32_t bD1 = smem_u32(&Bs[0][b_row + 8][b_col]);
    constexpr uint32_t A_STG = BM * BKP * 4;   // 10240
    constexpr uint32_t B_STG = BK * BNP * 4;   // 8704

    const float* gA0 = X + (size_t)(m0 + a_row)      * Uc + a_col;
    const float* gA1 = X + (size_t)(m0 + a_row + 64) * Uc + a_col;

    float acc[4][4][4];
#pragma unroll
    for (int mt = 0; mt < 4; ++mt)
#pragma unroll
        for (int nt = 0; nt < 4; ++nt)
#pragma unroll
            for (int e = 0; e < 4; ++e) acc[mt][nt][e] = 0.f;

    for (int g = g0; g <= g1; ++g) {
        const int sz0 = (sidx[a_row]      == g) ? 16 : 0;
        const int sz1 = (sidx[a_row + 64] == g) ? 16 : 0;
        const float* gB0 = W + (size_t)g * Uc * Vc + (size_t)b_row * Vc + n0 + b_col;
        const float* gB1 = gB0 + (size_t)8 * Vc;

        // prologue: stage 0 = k-tile 0
        cp16(aD0, gA0, sz0);
        cp16(aD1, gA1, sz1);
        cp16(bD0, gB0, 16);
        cp16(bD1, gB1, 16);
        cp_commit();

#pragma unroll 1
        for (int kt = 0; kt < KT; ++kt) {
            if (kt + 1 < KT) {
                const int k0 = (kt + 1) * BK;
                const uint32_t st = ((kt + 1) & 1);
                cp16(aD0 + st * A_STG, gA0 + k0, sz0);
                cp16(aD1 + st * A_STG, gA1 + k0, sz1);
                cp16(bD0 + st * B_STG, gB0 + (size_t)k0 * Vc, 16);
                cp16(bD1 + st * B_STG, gB1 + (size_t)k0 * Vc, 16);
                cp_commit();
                cp_wait<1>();
            } else {
                cp_wait<0>();
            }
            __syncthreads();

            const int buf = kt & 1;
#pragma unroll
            for (int ks = 0; ks < 2; ++ks) {
                const int kk = ks * 8;
                uint32_t af[4][4];
#pragma unroll
                for (int mt = 0; mt < 4; ++mt) {
                    const int r = wm * 64 + mt * 16 + lr;
                    af[mt][0] = f2tf(As[buf][r][kk + lq]);
                    af[mt][1] = f2tf(As[buf][r + 8][kk + lq]);
                    af[mt][2] = f2tf(As[buf][r][kk + lq + 4]);
                    af[mt][3] = f2tf(As[buf][r + 8][kk + lq + 4]);
                }
                uint32_t bf[4][2];
#pragma unroll
                for (int nt = 0; nt < 4; ++nt) {
                    const int cn = wn * 32 + nt * 8 + lr;
                    bf[nt][0] = f2tf(Bs[buf][kk + lq][cn]);
                    bf[nt][1] = f2tf(Bs[buf][kk + lq + 4][cn]);
                }
#pragma unroll
                for (int mt = 0; mt < 4; ++mt)
#pragma unroll
                    for (int nt = 0; nt < 4; ++nt)
                        mma_tf32(acc[mt][nt], af[mt], bf[nt]);
            }
            __syncthreads();
        }
    }

    const float scale = COEF[0];
#pragma unroll
    for (int mt = 0; mt < 4; ++mt) {
        const int r0 = m0 + wm * 64 + mt * 16 + lr;
#pragma unroll
        for (int nt = 0; nt < 4; ++nt) {
            const int col = n0 + wn * 32 + nt * 8 + 2 * lq;
            float2 v0, v1;
            v0.x = acc[mt][nt][0] * scale;
            v0.y = acc[mt][nt][1] * scale;
            v1.x = acc[mt][nt][2] * scale;
            v1.y = acc[mt][nt][3] * scale;
            *(float2*)(Y + (size_t)r0 * Vc + col)       = v0;
            *(float2*)(Y + (size_t)(r0 + 8) * Vc + col) = v1;
        }
    }
}

extern "C" void kernel_launch(void* const* d_in, const int* in_sizes, int n_in,
                              void* d_out, int out_size)
{
    const float* w    = nullptr;
    const float* x    = nullptr;
    const int*   idx  = nullptr;
    const float* coef = nullptr;
    for (int i = 0; i < n_in; ++i) {
        const long long sz = in_sizes[i];
        if      (sz == (long long)Cc * Uc * Vc) w    = (const float*)d_in[i];
        else if (sz == (long long)Zc * Uc)      x    = (const float*)d_in[i];
        else if (sz == (long long)Zc)           idx  = (const int*)d_in[i];
        else if (sz == 1)                       coef = (const float*)d_in[i];
    }
    if (!w    && n_in > 0) w    = (const float*)d_in[0];
    if (!x    && n_in > 1) x    = (const float*)d_in[1];
    if (!idx  && n_in > 2) idx  = (const int*)d_in[2];
    if (!coef && n_in > 3) coef = (const float*)d_in[3];

    float* y = (float*)d_out;

    dim3 grid(Vc / BN, Zc / BM);   // (4, 256)
    grouped_mma_kernel<<<grid, NT>>>(x, w, idx, coef, y);
}